// round 1
// baseline (speedup 1.0000x reference)
#include <cuda_runtime.h>
#include <cuda_bf16.h>

#define N_NODES 20000
#define N_EDGES 320000
#define F_IN   256
#define F_HID  512

// Scratch: (1+eps)*node_feat + segment_sum(msg)
__device__ float g_acc[N_NODES * F_IN];

// ---------------------------------------------------------------------------
// init: acc = (1+eps) * node_feat    (vectorized float4)
// ---------------------------------------------------------------------------
__global__ void init_acc_kernel(const float* __restrict__ node_feat,
                                const float* __restrict__ eps) {
    const float s = 1.0f + eps[0];
    int i = blockIdx.x * blockDim.x + threadIdx.x;  // float4 index
    float4 v = reinterpret_cast<const float4*>(node_feat)[i];
    v.x *= s; v.y *= s; v.z *= s; v.w *= s;
    reinterpret_cast<float4*>(g_acc)[i] = v;
}

// ---------------------------------------------------------------------------
// Fused 2-layer MLP (256 -> 512 -> 256) over a 64-row tile.
//   EDGE=true : X = edge_feat tile; epilogue: msg = relu(node_feat[src]+e),
//               atomicAdd into g_acc[dst]
//   EDGE=false: X = g_acc tile; epilogue: store to out
//
// Block: 256 threads = 16x16 grid; each thread owns a 4(row) x 8(col)
// micro-tile of a 64 x 128 output chunk.
// SMEM: Xs[64][260] + Hs[64][516] + Ws[16][128]  = 206,848 bytes
// ---------------------------------------------------------------------------
#define XS 260   // 256 + 4 pad (keeps 16B alignment, breaks bank conflicts)
#define HS 516   // 512 + 4 pad
#define SMEM_FLOATS (64 * XS + 64 * HS + 16 * 128)
#define SMEM_BYTES  (SMEM_FLOATS * 4)

template <bool EDGE>
__global__ void __launch_bounds__(256, 1)
mlp2_fused_kernel(const float* __restrict__ Xin,
                  const float* __restrict__ W1, const float* __restrict__ b1,
                  const float* __restrict__ W2, const float* __restrict__ b2,
                  const float* __restrict__ node_feat,
                  const int* __restrict__ src, const int* __restrict__ dst,
                  float* __restrict__ out, int M_total) {
    extern __shared__ float smem[];
    float* Xs = smem;                  // [64][XS]
    float* Hs = smem + 64 * XS;        // [64][HS]
    float* Ws = Hs + 64 * HS;          // [16][128]

    const float* X = EDGE ? Xin : g_acc;

    const int tid = threadIdx.x;
    const int tx = tid & 15;           // 0..15 -> cols tx*8 .. tx*8+7
    const int ty = tid >> 4;           // 0..15 -> rows ty*4 .. ty*4+3
    const int m0 = blockIdx.x * 64;

    // ---- load X tile [64][256] into SMEM (coalesced float4) ----
    for (int i = tid; i < 64 * 64; i += 256) {      // 64 float4 per row
        int r = i >> 6;
        int c = i & 63;
        int gr = m0 + r;
        if (gr >= M_total) gr = M_total - 1;        // clamp (safe read)
        float4 v = reinterpret_cast<const float4*>(X)[gr * 64 + c];
        *reinterpret_cast<float4*>(&Xs[r * XS + c * 4]) = v;
    }
    __syncthreads();

    // ================= GEMM 1:  H = relu(X @ W1 + b1)  [64 x 512] ==========
    for (int nc = 0; nc < 4; ++nc) {               // 4 chunks of 128 cols
        float acc[4][8];
        #pragma unroll
        for (int i = 0; i < 4; ++i)
            #pragma unroll
            for (int j = 0; j < 8; ++j) acc[i][j] = 0.0f;

        for (int kt = 0; kt < 16; ++kt) {          // K=256, BK=16
            __syncthreads();
            // stage W1[kt*16 .. +15][nc*128 .. +127] -> Ws[16][128]
            for (int i = tid; i < 512; i += 256) { // 512 float4
                int r = i >> 5;                    // 32 float4 per row
                int c4 = i & 31;
                *reinterpret_cast<float4*>(&Ws[r * 128 + c4 * 4]) =
                    reinterpret_cast<const float4*>(W1)[(kt * 16 + r) * 128 + nc * 32 + c4];
            }
            __syncthreads();

            #pragma unroll
            for (int k = 0; k < 16; ++k) {
                float a0 = Xs[(ty * 4 + 0) * XS + kt * 16 + k];
                float a1 = Xs[(ty * 4 + 1) * XS + kt * 16 + k];
                float a2 = Xs[(ty * 4 + 2) * XS + kt * 16 + k];
                float a3 = Xs[(ty * 4 + 3) * XS + kt * 16 + k];
                float4 bv0 = *reinterpret_cast<float4*>(&Ws[k * 128 + tx * 8]);
                float4 bv1 = *reinterpret_cast<float4*>(&Ws[k * 128 + tx * 8 + 4]);
                float bb[8] = {bv0.x, bv0.y, bv0.z, bv0.w, bv1.x, bv1.y, bv1.z, bv1.w};
                float aa[4] = {a0, a1, a2, a3};
                #pragma unroll
                for (int i = 0; i < 4; ++i)
                    #pragma unroll
                    for (int j = 0; j < 8; ++j)
                        acc[i][j] = fmaf(aa[i], bb[j], acc[i][j]);
            }
        }
        // bias + relu -> Hs
        float4 biasv0 = reinterpret_cast<const float4*>(b1)[nc * 32 + tx * 2];
        float4 biasv1 = reinterpret_cast<const float4*>(b1)[nc * 32 + tx * 2 + 1];
        float bias[8] = {biasv0.x, biasv0.y, biasv0.z, biasv0.w,
                         biasv1.x, biasv1.y, biasv1.z, biasv1.w};
        #pragma unroll
        for (int i = 0; i < 4; ++i) {
            float4 s0, s1;
            s0.x = fmaxf(acc[i][0] + bias[0], 0.0f);
            s0.y = fmaxf(acc[i][1] + bias[1], 0.0f);
            s0.z = fmaxf(acc[i][2] + bias[2], 0.0f);
            s0.w = fmaxf(acc[i][3] + bias[3], 0.0f);
            s1.x = fmaxf(acc[i][4] + bias[4], 0.0f);
            s1.y = fmaxf(acc[i][5] + bias[5], 0.0f);
            s1.z = fmaxf(acc[i][6] + bias[6], 0.0f);
            s1.w = fmaxf(acc[i][7] + bias[7], 0.0f);
            float* hp = &Hs[(ty * 4 + i) * HS + nc * 128 + tx * 8];
            *reinterpret_cast<float4*>(hp) = s0;
            *reinterpret_cast<float4*>(hp + 4) = s1;
        }
    }

    // ================= GEMM 2:  Eo = H @ W2 + b2  [64 x 256] ================
    for (int nc = 0; nc < 2; ++nc) {               // 2 chunks of 128 cols
        float acc[4][8];
        #pragma unroll
        for (int i = 0; i < 4; ++i)
            #pragma unroll
            for (int j = 0; j < 8; ++j) acc[i][j] = 0.0f;

        for (int kt = 0; kt < 32; ++kt) {          // K=512, BK=16
            __syncthreads();
            for (int i = tid; i < 512; i += 256) {
                int r = i >> 5;
                int c4 = i & 31;
                *reinterpret_cast<float4*>(&Ws[r * 128 + c4 * 4]) =
                    reinterpret_cast<const float4*>(W2)[(kt * 16 + r) * 64 + nc * 32 + c4];
            }
            __syncthreads();

            #pragma unroll
            for (int k = 0; k < 16; ++k) {
                float a0 = Hs[(ty * 4 + 0) * HS + kt * 16 + k];
                float a1 = Hs[(ty * 4 + 1) * HS + kt * 16 + k];
                float a2 = Hs[(ty * 4 + 2) * HS + kt * 16 + k];
                float a3 = Hs[(ty * 4 + 3) * HS + kt * 16 + k];
                float4 bv0 = *reinterpret_cast<float4*>(&Ws[k * 128 + tx * 8]);
                float4 bv1 = *reinterpret_cast<float4*>(&Ws[k * 128 + tx * 8 + 4]);
                float bb[8] = {bv0.x, bv0.y, bv0.z, bv0.w, bv1.x, bv1.y, bv1.z, bv1.w};
                float aa[4] = {a0, a1, a2, a3};
                #pragma unroll
                for (int i = 0; i < 4; ++i)
                    #pragma unroll
                    for (int j = 0; j < 8; ++j)
                        acc[i][j] = fmaf(aa[i], bb[j], acc[i][j]);
            }
        }

        // ---- epilogue ----
        const int cb = nc * 128 + tx * 8;
        float4 biasv0 = reinterpret_cast<const float4*>(b2)[cb >> 2];
        float4 biasv1 = reinterpret_cast<const float4*>(b2)[(cb >> 2) + 1];
        float bias[8] = {biasv0.x, biasv0.y, biasv0.z, biasv0.w,
                         biasv1.x, biasv1.y, biasv1.z, biasv1.w};

        #pragma unroll
        for (int i = 0; i < 4; ++i) {
            int gr = m0 + ty * 4 + i;
            if (gr >= M_total) continue;
            if (EDGE) {
                int s = src[gr];
                int d = dst[gr];
                float4 nf0 = reinterpret_cast<const float4*>(node_feat)[s * 64 + (cb >> 2)];
                float4 nf1 = reinterpret_cast<const float4*>(node_feat)[s * 64 + (cb >> 2) + 1];
                float nf[8] = {nf0.x, nf0.y, nf0.z, nf0.w, nf1.x, nf1.y, nf1.z, nf1.w};
                #pragma unroll
                for (int j = 0; j < 8; ++j) {
                    float v = fmaxf(acc[i][j] + bias[j] + nf[j], 0.0f);
                    atomicAdd(&g_acc[d * F_IN + cb + j], v);
                }
            } else {
                float4 s0, s1;
                s0.x = acc[i][0] + bias[0];
                s0.y = acc[i][1] + bias[1];
                s0.z = acc[i][2] + bias[2];
                s0.w = acc[i][3] + bias[3];
                s1.x = acc[i][4] + bias[4];
                s1.y = acc[i][5] + bias[5];
                s1.z = acc[i][6] + bias[6];
                s1.w = acc[i][7] + bias[7];
                float* op = &out[gr * F_IN + cb];
                *reinterpret_cast<float4*>(op) = s0;
                *reinterpret_cast<float4*>(op + 4) = s1;
            }
        }
    }
}

// ---------------------------------------------------------------------------
extern "C" void kernel_launch(void* const* d_in, const int* in_sizes, int n_in,
                              void* d_out, int out_size) {
    const float* node_feat = (const float*)d_in[0];
    const float* edge_feat = (const float*)d_in[1];
    const int*   src       = (const int*)d_in[2];
    const int*   dst       = (const int*)d_in[3];
    const float* We1       = (const float*)d_in[4];
    const float* be1       = (const float*)d_in[5];
    const float* We2       = (const float*)d_in[6];
    const float* be2       = (const float*)d_in[7];
    const float* Wn1       = (const float*)d_in[8];
    const float* bn1       = (const float*)d_in[9];
    const float* Wn2       = (const float*)d_in[10];
    const float* bn2       = (const float*)d_in[11];
    const float* eps       = (const float*)d_in[12];
    float* out = (float*)d_out;

    cudaFuncSetAttribute(mlp2_fused_kernel<true>,
                         cudaFuncAttributeMaxDynamicSharedMemorySize, SMEM_BYTES);
    cudaFuncSetAttribute(mlp2_fused_kernel<false>,
                         cudaFuncAttributeMaxDynamicSharedMemorySize, SMEM_BYTES);

    // 1) acc = (1+eps) * node_feat
    init_acc_kernel<<<(N_NODES * F_IN / 4) / 256, 256>>>(node_feat, eps);

    // 2) edge MLP + gather + relu + scatter-add   (320000 / 64 = 5000 blocks)
    mlp2_fused_kernel<true><<<N_EDGES / 64, 256, SMEM_BYTES>>>(
        edge_feat, We1, be1, We2, be2, node_feat, src, dst, nullptr, N_EDGES);

    // 3) node MLP on acc -> out                   (ceil(20000/64) = 313 blocks)
    mlp2_fused_kernel<false><<<(N_NODES + 63) / 64, 256, SMEM_BYTES>>>(
        nullptr, Wn1, bn1, Wn2, bn2, nullptr, nullptr, nullptr, out, N_NODES);
}

// round 7
// speedup vs baseline: 5.0530x; 5.0530x over previous
#include <cuda_runtime.h>
#include <cstdint>

#define N_NODES 20000
#define N_EDGES 320000
#define F_IN   256
#define F_HID  512

// ---------------- device scratch (no allocs allowed) ----------------
__device__ float g_acc[N_NODES * F_IN];          // (1+eps)*x + segment_sum
__device__ float g_W1T_e[F_HID * F_IN];          // [n=512][k=256] tf32 bits
__device__ float g_W2T_e[F_IN * F_HID];          // [n=256][k=512]
__device__ float g_W1T_n[F_HID * F_IN];
__device__ float g_W2T_n[F_IN * F_HID];

// ---------------- helpers ----------------
__device__ __forceinline__ float f2tf32(float x) {
    uint32_t o; asm("cvt.rna.tf32.f32 %0, %1;" : "=r"(o) : "f"(x));
    return __uint_as_float(o);
}
__device__ __forceinline__ float4 cvt4(float4 v) {
    v.x = f2tf32(v.x); v.y = f2tf32(v.y); v.z = f2tf32(v.z); v.w = f2tf32(v.w);
    return v;
}
// m16n8k8 tf32 mma: d += a * b   (A row-major 16x8, B col-major 8x8)
__device__ __forceinline__ void mma8(float* d, const float* a, float b0, float b1) {
    asm volatile(
        "mma.sync.aligned.m16n8k8.row.col.f32.tf32.tf32.f32 "
        "{%0,%1,%2,%3}, {%4,%5,%6,%7}, {%8,%9}, {%0,%1,%2,%3};"
        : "+f"(d[0]), "+f"(d[1]), "+f"(d[2]), "+f"(d[3])
        : "r"(__float_as_uint(a[0])), "r"(__float_as_uint(a[1])),
          "r"(__float_as_uint(a[2])), "r"(__float_as_uint(a[3])),
          "r"(__float_as_uint(b0)),   "r"(__float_as_uint(b1)));
}

// ---------------- misc kernels ----------------
__global__ void init_acc_kernel(const float* __restrict__ node_feat,
                                const float* __restrict__ eps) {
    const float s = 1.0f + eps[0];
    int i = blockIdx.x * blockDim.x + threadIdx.x;
    float4 v = reinterpret_cast<const float4*>(node_feat)[i];
    v.x *= s; v.y *= s; v.z *= s; v.w *= s;
    reinterpret_cast<float4*>(g_acc)[i] = v;
}

// out[n*K + k] = tf32(in[k*N + n])   (in: [K, N])
__global__ void transpose_cvt_kernel(const float* __restrict__ in,
                                     float* __restrict__ out, int K, int N) {
    int idx = blockIdx.x * blockDim.x + threadIdx.x;
    if (idx >= K * N) return;
    int n = idx / K;
    int k = idx - n * K;
    out[idx] = f2tf32(in[k * N + n]);
}

// ---------------- fused 2-layer MLP on mma.sync tf32 ----------------
// Per CTA: 128 rows, 256 threads (8 warps, 4 warp-rows x 2 warp-cols).
// GEMM1 out chunk 128x64 (warp tile 32x32), 8 hidden chunks;
// GEMM2 accumulates 128x256 in registers (warp tile 32x128).
// SMEM (floats):
//   Xs  [128][260]   0      (33280)  pad 260: (4*grp+tig)%32 distinct
//   Hs  [128][68]    33280  (8704)   pad 68:  same property
//   W1s [64][36]     41984  (2304)   pad 36:  (4n+k)%32 distinct
//   W2s [256][36]    44288  (9216)
//   b1s [512]        53504
//   b2s [256]        54016          total 54272 floats = 217088 B
#define OFF_HS  33280
#define OFF_W1  41984
#define OFF_W2  44288
#define OFF_B1  53504
#define OFF_B2  54016
#define SMEM_FLOATS 54272
#define SMEM_BYTES  (SMEM_FLOATS * 4)

template <bool EDGE>
__global__ void __launch_bounds__(256, 1)
gine_mma(const float* __restrict__ Xin,
         const float* __restrict__ W1T, const float* __restrict__ b1,
         const float* __restrict__ W2T, const float* __restrict__ b2,
         const float* __restrict__ node_feat,
         const int* __restrict__ src, const int* __restrict__ dst,
         float* __restrict__ out, int M_total) {
    extern __shared__ float sm[];
    float* Xs  = sm;
    float* Hs  = sm + OFF_HS;
    float* W1s = sm + OFF_W1;
    float* W2s = sm + OFF_W2;
    float* b1s = sm + OFF_B1;
    float* b2s = sm + OFF_B2;

    const int tid  = threadIdx.x;
    const int lane = tid & 31;
    const int grp  = lane >> 2;     // 0..7
    const int tig  = lane & 3;      // 0..3
    const int wid  = tid >> 5;
    const int wr   = wid & 3;       // warp row: rows wr*32..+31
    const int wc   = wid >> 2;      // warp col: 0..1
    const int m0   = blockIdx.x * 128;

    const float4* X4   = reinterpret_cast<const float4*>(Xin);
    const float4* W1T4 = reinterpret_cast<const float4*>(W1T);
    const float4* W2T4 = reinterpret_cast<const float4*>(W2T);

    // stage biases
    for (int i = tid; i < 512; i += 256) b1s[i] = b1[i];
    b2s[tid] = b2[tid];

    // stage X tile [128][256] -> tf32 (coalesced float4)
    #pragma unroll
    for (int it = 0; it < 32; ++it) {
        int i = it * 256 + tid;
        int r = i >> 6, c4 = i & 63;
        int gr = m0 + r; if (gr >= M_total) gr = M_total - 1;
        float4 v = cvt4(X4[gr * 64 + c4]);
        *reinterpret_cast<float4*>(Xs + r * 260 + c4 * 4) = v;
    }

    float acc2[2][16][4];
    #pragma unroll
    for (int mi = 0; mi < 2; ++mi)
        #pragma unroll
        for (int ni = 0; ni < 16; ++ni)
            #pragma unroll
            for (int q = 0; q < 4; ++q) acc2[mi][ni][q] = 0.f;

    for (int hc = 0; hc < 8; ++hc) {
        // ===== GEMM1: H chunk [128 x 64] = X @ W1T[hc*64..][k] =====
        float acc1[2][4][4];
        #pragma unroll
        for (int mi = 0; mi < 2; ++mi)
            #pragma unroll
            for (int ni = 0; ni < 4; ++ni)
                #pragma unroll
                for (int q = 0; q < 4; ++q) acc1[mi][ni][q] = 0.f;

        for (int kt = 0; kt < 8; ++kt) {        // K=256, slices of 32
            __syncthreads();                    // W1s reuse safe; 1st iter: X/bias visible
            #pragma unroll
            for (int it = 0; it < 2; ++it) {    // 512 float4
                int i = it * 256 + tid;
                int r = i >> 3, g = i & 7;
                float4 v = W1T4[(hc * 64 + r) * 64 + kt * 8 + g];
                *reinterpret_cast<float4*>(W1s + r * 36 + g * 4) = v;
            }
            __syncthreads();
            #pragma unroll
            for (int k8 = 0; k8 < 4; ++k8) {
                const int kb = kt * 32 + k8 * 8;
                float a[2][4];
                #pragma unroll
                for (int mi = 0; mi < 2; ++mi) {
                    int row = wr * 32 + mi * 16;
                    a[mi][0] = Xs[(row + grp    ) * 260 + kb + tig];
                    a[mi][1] = Xs[(row + grp + 8) * 260 + kb + tig];
                    a[mi][2] = Xs[(row + grp    ) * 260 + kb + tig + 4];
                    a[mi][3] = Xs[(row + grp + 8) * 260 + kb + tig + 4];
                }
                #pragma unroll
                for (int ni = 0; ni < 4; ++ni) {
                    int nb = wc * 32 + ni * 8;
                    float b0  = W1s[(nb + grp) * 36 + k8 * 8 + tig];
                    float bv1 = W1s[(nb + grp) * 36 + k8 * 8 + tig + 4];
                    mma8(acc1[0][ni], a[0], b0, bv1);
                    mma8(acc1[1][ni], a[1], b0, bv1);
                }
            }
        }
        // epilogue1: Hs = tf32(relu(acc1 + b1))  (each warp writes its own tile)
        #pragma unroll
        for (int mi = 0; mi < 2; ++mi)
            #pragma unroll
            for (int ni = 0; ni < 4; ++ni) {
                int row = wr * 32 + mi * 16 + grp;
                int col = wc * 32 + ni * 8 + 2 * tig;
                float bb0 = b1s[hc * 64 + col];
                float bb1 = b1s[hc * 64 + col + 1];
                Hs[row * 68 + col]           = f2tf32(fmaxf(acc1[mi][ni][0] + bb0, 0.f));
                Hs[row * 68 + col + 1]       = f2tf32(fmaxf(acc1[mi][ni][1] + bb1, 0.f));
                Hs[(row + 8) * 68 + col]     = f2tf32(fmaxf(acc1[mi][ni][2] + bb0, 0.f));
                Hs[(row + 8) * 68 + col + 1] = f2tf32(fmaxf(acc1[mi][ni][3] + bb1, 0.f));
            }
        // ===== GEMM2 partial: acc2 += Hchunk @ W2T[:, hc*64..+64) =====
        for (int kt2 = 0; kt2 < 2; ++kt2) {
            __syncthreads();                    // Hs visible; W2s reuse safe
            #pragma unroll
            for (int it = 0; it < 8; ++it) {    // 2048 float4
                int i = it * 256 + tid;
                int r = i >> 3, g = i & 7;
                float4 v = W2T4[r * 128 + hc * 16 + kt2 * 8 + g];
                *reinterpret_cast<float4*>(W2s + r * 36 + g * 4) = v;
            }
            __syncthreads();
            #pragma unroll
            for (int k8 = 0; k8 < 4; ++k8) {
                const int kb = kt2 * 32 + k8 * 8;
                float a[2][4];
                #pragma unroll
                for (int mi = 0; mi < 2; ++mi) {
                    int row = wr * 32 + mi * 16;
                    a[mi][0] = Hs[(row + grp    ) * 68 + kb + tig];
                    a[mi][1] = Hs[(row + grp + 8) * 68 + kb + tig];
                    a[mi][2] = Hs[(row + grp    ) * 68 + kb + tig + 4];
                    a[mi][3] = Hs[(row + grp + 8) * 68 + kb + tig + 4];
                }
                #pragma unroll
                for (int ni = 0; ni < 16; ++ni) {
                    int nb = wc * 128 + ni * 8;
                    float b0  = W2s[(nb + grp) * 36 + k8 * 8 + tig];
                    float bv1 = W2s[(nb + grp) * 36 + k8 * 8 + tig + 4];
                    mma8(acc2[0][ni], a[0], b0, bv1);
                    mma8(acc2[1][ni], a[1], b0, bv1);
                }
            }
        }
    }

    // ===== final epilogue: restage acc2 -> Xs (free now) for coalescing =====
    __syncthreads();
    #pragma unroll
    for (int mi = 0; mi < 2; ++mi)
        #pragma unroll
        for (int ni = 0; ni < 16; ++ni) {
            int row = wr * 32 + mi * 16 + grp;
            int col = wc * 128 + ni * 8 + 2 * tig;
            Xs[row * 260 + col]           = acc2[mi][ni][0];
            Xs[row * 260 + col + 1]       = acc2[mi][ni][1];
            Xs[(row + 8) * 260 + col]     = acc2[mi][ni][2];
            Xs[(row + 8) * 260 + col + 1] = acc2[mi][ni][3];
        }
    __syncthreads();

    // coalesced output: 4 rows x 64 float4 per iteration
    #pragma unroll 4
    for (int it = 0; it < 32; ++it) {
        int r  = it * 4 + (tid >> 6);
        int c4 = tid & 63;
        int gr = m0 + r;
        float4 v = *reinterpret_cast<float4*>(Xs + r * 260 + c4 * 4);
        float4 bb = *reinterpret_cast<float4*>(b2s + c4 * 4);
        v.x += bb.x; v.y += bb.y; v.z += bb.z; v.w += bb.w;
        if (EDGE) {
            int s = src[gr];
            int d = dst[gr];
            float4 nf = reinterpret_cast<const float4*>(node_feat)[s * 64 + c4];
            v.x = fmaxf(v.x + nf.x, 0.f);
            v.y = fmaxf(v.y + nf.y, 0.f);
            v.z = fmaxf(v.z + nf.z, 0.f);
            v.w = fmaxf(v.w + nf.w, 0.f);
            float* p = g_acc + (size_t)d * 256 + c4 * 4;
            asm volatile("red.global.add.v4.f32 [%0], {%1, %2, %3, %4};"
                         :: "l"(p), "f"(v.x), "f"(v.y), "f"(v.z), "f"(v.w)
                         : "memory");
        } else if (gr < M_total) {
            reinterpret_cast<float4*>(out)[gr * 64 + c4] = v;
        }
    }
}

// ---------------------------------------------------------------------------
extern "C" void kernel_launch(void* const* d_in, const int* in_sizes, int n_in,
                              void* d_out, int out_size) {
    const float* node_feat = (const float*)d_in[0];
    const float* edge_feat = (const float*)d_in[1];
    const int*   src       = (const int*)d_in[2];
    const int*   dst       = (const int*)d_in[3];
    const float* We1       = (const float*)d_in[4];
    const float* be1       = (const float*)d_in[5];
    const float* We2       = (const float*)d_in[6];
    const float* be2       = (const float*)d_in[7];
    const float* Wn1       = (const float*)d_in[8];
    const float* bn1       = (const float*)d_in[9];
    const float* Wn2       = (const float*)d_in[10];
    const float* bn2       = (const float*)d_in[11];
    const float* eps       = (const float*)d_in[12];
    float* out = (float*)d_out;

    cudaFuncSetAttribute(gine_mma<true>,
                         cudaFuncAttributeMaxDynamicSharedMemorySize, SMEM_BYTES);
    cudaFuncSetAttribute(gine_mma<false>,
                         cudaFuncAttributeMaxDynamicSharedMemorySize, SMEM_BYTES);

    float *W1Te, *W2Te, *W1Tn, *W2Tn, *accp;
    cudaGetSymbolAddress((void**)&W1Te, g_W1T_e);
    cudaGetSymbolAddress((void**)&W2Te, g_W2T_e);
    cudaGetSymbolAddress((void**)&W1Tn, g_W1T_n);
    cudaGetSymbolAddress((void**)&W2Tn, g_W2T_n);
    cudaGetSymbolAddress((void**)&accp, g_acc);

    // 1) acc = (1+eps)*node_feat
    init_acc_kernel<<<(N_NODES * F_IN / 4) / 256, 256>>>(node_feat, eps);

    // 2) weight transpose + tf32 convert
    transpose_cvt_kernel<<<512, 256>>>(We1, W1Te, F_IN,  F_HID);
    transpose_cvt_kernel<<<512, 256>>>(We2, W2Te, F_HID, F_IN);
    transpose_cvt_kernel<<<512, 256>>>(Wn1, W1Tn, F_IN,  F_HID);
    transpose_cvt_kernel<<<512, 256>>>(Wn2, W2Tn, F_HID, F_IN);

    // 3) edge MLP + gather/relu/scatter-add  (320000/128 = 2500 CTAs)
    gine_mma<true><<<N_EDGES / 128, 256, SMEM_BYTES>>>(
        edge_feat, W1Te, be1, W2Te, be2, node_feat, src, dst, nullptr, N_EDGES);

    // 4) node MLP on acc -> out              (ceil(20000/128) = 157 CTAs)
    gine_mma<false><<<(N_NODES + 127) / 128, 256, SMEM_BYTES>>>(
        accp, W1Tn, bn1, W2Tn, bn2, nullptr, nullptr, nullptr, out, N_NODES);
}